// round 15
// baseline (speedup 1.0000x reference)
#include <cuda_runtime.h>
#include <cuda_bf16.h>
#include <mma.h>
#include <cstdint>

using namespace nvcuda;
using bf16 = __nv_bfloat16;
using u64 = unsigned long long;

// ---------------------------------------------------------------------------
// CMAFM pipeline, WMMA bf16 split-2 (3 terms, fp32 accum, ~5e-6 rel).
// All GEMM inputs are pre-split bf16 hi/lo pairs in global. Every GEMM is a
// CIN=128 pass (CIN=256 ops = 2 accumulation passes via fp32 tmp).
// gemm_k: 1 CTA/SM (174KB smem), CTA = 256 px; W (hi+lo, K=128) resident;
// X double-buffered with cp.async prefetch pipelined across subtiles.
// ---------------------------------------------------------------------------

#define TB 256

constexpr int WWI = 256, XP = 132;
constexpr int ABUF = 64 * XP;
constexpr size_t NTOT = 4ull * 128 * 256 * 256;
constexpr int IMG = 65536, BSTRIDE = 128 * IMG;

__device__ __align__(16) float g_scr[5ull * NTOT];
__device__ __align__(16) bf16  g_bf[12ull * NTOT];
__device__ __align__(16) bf16  g_w2[458752];
enum { OW_QO = 0,      OW_KO = 32768,  OW_VO = 65536,  OW_QS = 98304,
       OW_KS = 131072, OW_VS = 163840, OW_PO = 196608, OW_PS = 229376,
       OW_GO = 262144, OW_GS = 327680, OW_FW = 393216 };

enum { EPI_NONE = 0, EPI_BIAS = 1, EPI_PROJ = 2, EPI_GATEACC = 3, EPI_FUSEACC = 4 };

// smem byte layout
constexpr int WPIT = 136;                 // W pitch (bf16)
constexpr int XPIT = 72;                  // X pitch (bf16)
constexpr int DPIT = 68;                  // D pitch (fp32)
constexpr int WPL  = 128 * WPIT * 2;      // 34816 per W plane
constexpr int XBUFB = 2 * 128 * XPIT * 2; // 36864 per X buffer (hi+lo)
constexpr int XB0  = 2 * WPL;             // 69632
constexpr int XB1  = XB0 + XBUFB;         // 106496
constexpr int DOFF = XB1 + XBUFB;         // 143360
constexpr int SMEM_G = DOFF + 128 * DPIT * 4;  // 178176
constexpr int SMEM_A = 3 * ABUF * 4;           // 101376

struct GP {
    const bf16*  xh[6];       // X pair hi base (lo = +NTOT)
    const bf16*  wh[6];       // W hi plane
    const bf16*  wl[6];       // W lo plane
    int          wstride;     // 128 or 256
    const float* bias[6];
    float*       dst[6];      // fp32 out / sigma
    bf16*        dpair[6];    // pair out
    const float* acc[6];      // accumulate input (ACC epilogues)
    const float* f32a[6];     // GATE: F
    const float* f32b[6];     // GATE: F_proj
    const float *gma, *bta, *mu, *var;
};
struct AP { const float *q0, *k0, *v0, *q1, *k1, *v1; bf16 *o0, *o1; };
struct PPP { const float* w[11]; };

// ---- helpers --------------------------------------------------------------
__device__ __forceinline__ void f2fma(u64& d, u64 a, u64 b) {
    asm("fma.rn.f32x2 %0, %1, %2, %0;" : "+l"(d) : "l"(a), "l"(b));
}
__device__ __forceinline__ u64 f2mul(u64 a, u64 b) {
    u64 d; asm("mul.rn.f32x2 %0, %1, %2;" : "=l"(d) : "l"(a), "l"(b)); return d;
}
__device__ __forceinline__ u64 f2add(u64 a, u64 b) {
    u64 d; asm("add.rn.f32x2 %0, %1, %2;" : "=l"(d) : "l"(a), "l"(b)); return d;
}
__device__ __forceinline__ u64 dup2(float v) {
    u64 d; asm("mov.b64 %0, {%1, %1};" : "=l"(d) : "f"(v)); return d;
}
__device__ __forceinline__ float f2sum(u64 a) {
    float lo, hi; asm("mov.b64 {%0, %1}, %2;" : "=f"(lo), "=f"(hi) : "l"(a));
    return lo + hi;
}
__device__ __forceinline__ void cp16(uint32_t s, const void* g) {
    asm volatile("cp.async.cg.shared.global [%0], [%1], 16;" :: "r"(s), "l"(g));
}
__device__ __forceinline__ float sigmoidf_(float x) {
    return 1.f / (1.f + __expf(-x));
}
__device__ __forceinline__ void split2(float v, bf16& h, bf16& l) {
    h = __float2bfloat16_rn(v);
    l = __float2bfloat16_rn(v - __bfloat162float(h));
}

// ---------------------------------------------------------------------------
__global__ void preproc_all(PPP pp) {
    const int bidx = blockIdx.x;
    int n, off, i;
    const float* W;
    if (bidx < 512) {
        const int m = bidx >> 6;
        n = 16384; off = m * 32768;
        i = ((bidx & 63) << 8) + threadIdx.x;
        W = pp.w[m];
    } else {
        const int bb = bidx - 512, m = bb >> 7;
        n = 32768; off = 262144 + m * 65536;
        i = ((bb & 127) << 8) + threadIdx.x;
        W = pp.w[8 + m];
    }
    float x = W[i];
    bf16 h, l; split2(x, h, l);
    g_w2[off + i] = h;
    g_w2[off + n + i] = l;
}

__global__ void conv_pair(const float* __restrict__ a, const float* __restrict__ b,
                          bf16* pa, bf16* pb) {
    const float* src; bf16* dh;
    if (blockIdx.x < 4096) { src = a; dh = pa; }
    else                   { src = b; dh = pb; }
    const size_t base = (size_t)(blockIdx.x & 4095) * 8192 + threadIdx.x * 4;
#pragma unroll
    for (int j = 0; j < 8; ++j) {
        const size_t off = base + j * 1024;
        float4 v = *(const float4*)(src + off);
        bf16 h0, h1, h2, h3, l0, l1, l2, l3;
        split2(v.x, h0, l0); split2(v.y, h1, l1);
        split2(v.z, h2, l2); split2(v.w, h3, l3);
        *(__nv_bfloat162*)(dh + off)     = __nv_bfloat162{h0, h1};
        *(__nv_bfloat162*)(dh + off + 2) = __nv_bfloat162{h2, h3};
        *(__nv_bfloat162*)(dh + NTOT + off)     = __nv_bfloat162{l0, l1};
        *(__nv_bfloat162*)(dh + NTOT + off + 2) = __nv_bfloat162{l2, l3};
    }
}

// ---------------------------------------------------------------------------
// Pipelined GEMM pass: D[128 ch][px] += W[128][128] . X[128][px] (+ epilogue).
// grid = nMat * 1024; m = blockIdx.x >> 10. CTA = 256 px = 4 subtiles x 64.
// ---------------------------------------------------------------------------
extern __shared__ char smem_g[];

template <int EPI>
__global__ void __launch_bounds__(TB, 1) gemm_k(GP p) {
    const int tid = threadIdx.x;
    const int w = tid >> 5;
    const int m = blockIdx.x >> 10;
    const int px0 = (blockIdx.x & 1023) << 8;
    const int b = px0 >> 16;
    const int hw0 = px0 & (IMG - 1);

    uint32_t sbase;
    asm("{ .reg .u64 t; cvta.to.shared.u64 t, %1; cvt.u32.u64 %0, t; }"
        : "=r"(sbase) : "l"(smem_g));
    bf16* WH = (bf16*)smem_g;
    bf16* WL = (bf16*)(smem_g + WPL);
    float* Dsm = (float*)(smem_g + DOFF);

    const bf16* xh = p.xh[m];
    const bf16* xl = xh + NTOT;
    const int ws = p.wstride;

    // stage W (hi+lo), group 0
    {
        const bf16* wh = p.wh[m];
        const bf16* wl = p.wl[m];
#pragma unroll
        for (int it = 0; it < 8; ++it) {
            const int s = tid + it * TB;          // 0..2047
            const int r = s >> 4, sg = s & 15;
            cp16(sbase + (r * WPIT + sg * 8) * 2, wh + r * ws + sg * 8);
            cp16(sbase + WPL + (r * WPIT + sg * 8) * 2, wl + r * ws + sg * 8);
        }
    }
    // stage X[0]
    {
        const size_t ga = (size_t)b * BSTRIDE + hw0;
#pragma unroll
        for (int it = 0; it < 4; ++it) {
            const int s = tid + it * TB;
            const int r = s >> 3, sg = s & 7;
            const size_t go = ga + (size_t)r * IMG + sg * 8;
            cp16(sbase + XB0 + (r * XPIT + sg * 8) * 2, xh + go);
            cp16(sbase + XB0 + 128 * XPIT * 2 + (r * XPIT + sg * 8) * 2, xl + go);
        }
    }
    asm volatile("cp.async.commit_group;");

    const int c = tid >> 1, q = tid & 1;
    const float bias_c = (EPI == EPI_NONE) ? 0.f : __ldg(p.bias[m] + c);
    float inv_c = 0.f, sh_c = 0.f;
    if (EPI == EPI_FUSEACC) {
        inv_c = __ldg(p.gma + c) * rsqrtf(__ldg(p.var + c) + 1e-5f);
        sh_c  = __ldg(p.bta + c) - __ldg(p.mu + c) * inv_c;
    }

    wmma::fragment<wmma::accumulator, 16, 16, 16, float> acc[4];

    for (int sub = 0; sub < 4; ++sub) {
        asm volatile("cp.async.wait_group 0;");
        __syncthreads();      // X[sub] visible; epilogue reads of Dsm done

        if (sub < 3) {        // prefetch X[sub+1] into the other buffer
            const int hw = hw0 + (sub + 1) * 64;
            const uint32_t xb = sbase + (((sub + 1) & 1) ? XB1 : XB0);
            const size_t ga = (size_t)b * BSTRIDE + hw;
#pragma unroll
            for (int it = 0; it < 4; ++it) {
                const int s = tid + it * TB;
                const int r = s >> 3, sg = s & 7;
                const size_t go = ga + (size_t)r * IMG + sg * 8;
                cp16(xb + (r * XPIT + sg * 8) * 2, xh + go);
                cp16(xb + 128 * XPIT * 2 + (r * XPIT + sg * 8) * 2, xl + go);
            }
            asm volatile("cp.async.commit_group;");
        }

        bf16* XH = (bf16*)(smem_g + ((sub & 1) ? XB1 : XB0));
        bf16* XL = XH + 128 * XPIT;

#pragma unroll
        for (int nt = 0; nt < 4; ++nt) wmma::fill_fragment(acc[nt], 0.0f);
        const bf16* Ah = WH + w * 16 * WPIT;
        const bf16* Al = WL + w * 16 * WPIT;
#pragma unroll
        for (int kk = 0; kk < 8; ++kk) {
            wmma::fragment<wmma::matrix_a, 16, 16, 16, bf16, wmma::row_major> ah, al;
            wmma::load_matrix_sync(ah, Ah + kk * 16, WPIT);
            wmma::load_matrix_sync(al, Al + kk * 16, WPIT);
#pragma unroll
            for (int nt = 0; nt < 4; ++nt) {
                wmma::fragment<wmma::matrix_b, 16, 16, 16, bf16, wmma::row_major> bh, bl;
                wmma::load_matrix_sync(bh, XH + kk * 16 * XPIT + nt * 16, XPIT);
                wmma::load_matrix_sync(bl, XL + kk * 16 * XPIT + nt * 16, XPIT);
                wmma::mma_sync(acc[nt], ah, bh, acc[nt]);
                wmma::mma_sync(acc[nt], ah, bl, acc[nt]);
                wmma::mma_sync(acc[nt], al, bh, acc[nt]);
            }
        }

#pragma unroll
        for (int nt = 0; nt < 4; ++nt)
            wmma::store_matrix_sync(Dsm + w * 16 * DPIT + nt * 16, acc[nt], DPIT,
                                    wmma::mem_row_major);
        __syncthreads();

        // scalar epilogue: thread owns (channel c, 32-px half q)
        {
            const int hw = hw0 + sub * 64;
            const size_t ga = (size_t)b * BSTRIDE + (size_t)c * IMG + hw + q * 32;
            const float* dp = Dsm + c * DPIT + q * 32;
#pragma unroll
            for (int j = 0; j < 8; ++j) {
                float4 v = *(const float4*)(dp + j * 4);
                const size_t o = ga + j * 4;
                if (EPI == EPI_NONE) {
                    *(float4*)(p.dst[m] + o) = v;
                    continue;
                }
                v.x += bias_c; v.y += bias_c; v.z += bias_c; v.w += bias_c;
                if (EPI == EPI_BIAS) {
                    *(float4*)(p.dst[m] + o) = v;
                } else if (EPI == EPI_PROJ) {
                    *(float4*)(p.dst[m] + o) = v;
                    bf16 h0, h1, h2, h3, l0, l1, l2, l3;
                    split2(v.x, h0, l0); split2(v.y, h1, l1);
                    split2(v.z, h2, l2); split2(v.w, h3, l3);
                    bf16* dph = p.dpair[m];
                    *(__nv_bfloat162*)(dph + o)     = __nv_bfloat162{h0, h1};
                    *(__nv_bfloat162*)(dph + o + 2) = __nv_bfloat162{h2, h3};
                    *(__nv_bfloat162*)(dph + NTOT + o)     = __nv_bfloat162{l0, l1};
                    *(__nv_bfloat162*)(dph + NTOT + o + 2) = __nv_bfloat162{l2, l3};
                } else if (EPI == EPI_GATEACC) {
                    float4 t = *(const float4*)(p.acc[m] + o);
                    v.x += t.x; v.y += t.y; v.z += t.z; v.w += t.w;
                    float4 f  = *(const float4*)(p.f32a[m] + o);
                    float4 fc = *(const float4*)(p.f32b[m] + o);
                    float4 s;
                    s.x = sigmoidf_(v.x); s.y = sigmoidf_(v.y);
                    s.z = sigmoidf_(v.z); s.w = sigmoidf_(v.w);
                    *(float4*)(p.dst[m] + o) = s;
                    float4 r;
                    r.x = f.x + s.x * fc.x; r.y = f.y + s.y * fc.y;
                    r.z = f.z + s.z * fc.z; r.w = f.w + s.w * fc.w;
                    bf16 h0, h1, h2, h3, l0, l1, l2, l3;
                    split2(r.x, h0, l0); split2(r.y, h1, l1);
                    split2(r.z, h2, l2); split2(r.w, h3, l3);
                    bf16* dph = p.dpair[m];
                    *(__nv_bfloat162*)(dph + o)     = __nv_bfloat162{h0, h1};
                    *(__nv_bfloat162*)(dph + o + 2) = __nv_bfloat162{h2, h3};
                    *(__nv_bfloat162*)(dph + NTOT + o)     = __nv_bfloat162{l0, l1};
                    *(__nv_bfloat162*)(dph + NTOT + o + 2) = __nv_bfloat162{l2, l3};
                } else {  // EPI_FUSEACC
                    float4 t = *(const float4*)(p.acc[m] + o);
                    v.x += t.x; v.y += t.y; v.z += t.z; v.w += t.w;
                    float4 r;
                    r.x = v.x * inv_c + sh_c; r.y = v.y * inv_c + sh_c;
                    r.z = v.z * inv_c + sh_c; r.w = v.w * inv_c + sh_c;
                    r.x *= sigmoidf_(r.x); r.y *= sigmoidf_(r.y);
                    r.z *= sigmoidf_(r.z); r.w *= sigmoidf_(r.w);
                    *(float4*)(p.dst[m] + o) = r;
                }
            }
        }
    }
}

// ---------------------------------------------------------------------------
// Fused dual-direction window attention (SIMT fp32, validated); epilogue
// writes the bf16 hi/lo pair consumed by the projection GEMMs.
// ---------------------------------------------------------------------------
__device__ __forceinline__ void load_window(float* dst, const float* __restrict__ src,
                                            int gbase, int tid) {
    const int c = tid >> 1, qq = tid & 1;
    const float* s = src + gbase + c * IMG + qq * 4;
#pragma unroll
    for (int i = 0; i < 8; ++i) {
        float4 v = *(const float4*)(s + i * WWI);
        float* d = dst + (i * 8 + qq * 4) * XP + c;
        d[0] = v.x; d[XP] = v.y; d[2 * XP] = v.z; d[3 * XP] = v.w;
    }
}
__device__ __forceinline__ void store_window_pair(bf16* __restrict__ hi,
                                                  const float* sbuf, int gbase, int tid) {
    const int c = tid >> 1, qq = tid & 1;
    bf16* gh = hi + gbase + c * IMG + qq * 4;
    bf16* gl = gh + NTOT;
    const float* sp0 = sbuf + qq * 4 * XP + c;
#pragma unroll
    for (int i = 0; i < 8; ++i) {
        const float* sp = sp0 + i * 8 * XP;
        bf16 h0, h1, h2, h3, l0, l1, l2, l3;
        split2(sp[0], h0, l0);      split2(sp[XP], h1, l1);
        split2(sp[2 * XP], h2, l2); split2(sp[3 * XP], h3, l3);
        *(__nv_bfloat162*)(gh + i * WWI)     = __nv_bfloat162{h0, h1};
        *(__nv_bfloat162*)(gh + i * WWI + 2) = __nv_bfloat162{h2, h3};
        *(__nv_bfloat162*)(gl + i * WWI)     = __nv_bfloat162{l0, l1};
        *(__nv_bfloat162*)(gl + i * WWI + 2) = __nv_bfloat162{l2, l3};
    }
}

__global__ void __launch_bounds__(TB, 2) attn_k(AP a) {
    float* smem = (float*)smem_g;
    float* BQ = smem;
    float* BK = smem + ABUF;
    float* BV = smem + 2 * ABUF;

    const int tid = threadIdx.x;
    const int dir = blockIdx.x >> 12;
    const int widx = blockIdx.x & 4095;
    const float* Q = dir ? a.q1 : a.q0;
    const float* K = dir ? a.k1 : a.k0;
    const float* V = dir ? a.v1 : a.v0;
    bf16* O = dir ? a.o1 : a.o0;

    const int b = widx >> 10;
    const int wh = (widx >> 5) & 31;
    const int ww = widx & 31;
    const int gbase = b * BSTRIDE + (wh * 8) * WWI + ww * 8;

    load_window(BQ, Q, gbase, tid);
    load_window(BK, K, gbase, tid);
    load_window(BV, V, gbase, tid);
    __syncthreads();

    const int L = tid & 31, w = tid >> 5;
    const int head = w >> 1;
    const int row = (w & 1) * 32 + L;

    u64 q[16];
    {
        const ulonglong2* qp = (const ulonglong2*)(BQ + row * XP + head * 32);
        const u64 sc2 = dup2(0.17677669529663687f);  // 32^-0.5
#pragma unroll
        for (int t = 0; t < 8; ++t) {
            ulonglong2 v = qp[t];
            q[2 * t]     = f2mul(v.x, sc2);
            q[2 * t + 1] = f2mul(v.y, sc2);
        }
    }
    __syncthreads();

    const float* kbase = BK + head * 32;
    const float* vbase = BV + head * 32;
    float l = 0.f;
    u64 o[16];
#pragma unroll
    for (int t = 0; t < 16; ++t) o[t] = 0ull;

    for (int j = 0; j < 64; ++j) {
        const ulonglong2* kp = (const ulonglong2*)(kbase + j * XP);
        u64 d0 = 0ull, d1 = 0ull, d2 = 0ull, d3 = 0ull;
#pragma unroll
        for (int t = 0; t < 4; ++t) {
            ulonglong2 ka = kp[2 * t], kb = kp[2 * t + 1];
            f2fma(d0, q[4 * t],     ka.x);
            f2fma(d1, q[4 * t + 1], ka.y);
            f2fma(d2, q[4 * t + 2], kb.x);
            f2fma(d3, q[4 * t + 3], kb.y);
        }
        const float e = __expf(f2sum(f2add(f2add(d0, d1), f2add(d2, d3))));
        l += e;
        const u64 ee = dup2(e);
        const ulonglong2* vp = (const ulonglong2*)(vbase + j * XP);
#pragma unroll
        for (int t = 0; t < 8; ++t) {
            ulonglong2 v2 = vp[t];
            f2fma(o[2 * t],     ee, v2.x);
            f2fma(o[2 * t + 1], ee, v2.y);
        }
    }
    const u64 inv2 = dup2(1.f / l);
    ulonglong2* op = (ulonglong2*)(BQ + row * XP + head * 32);
#pragma unroll
    for (int t = 0; t < 8; ++t) {
        ulonglong2 r;
        r.x = f2mul(o[2 * t], inv2);
        r.y = f2mul(o[2 * t + 1], inv2);
        op[t] = r;
    }
    __syncthreads();
    store_window_pair(O, BQ, gbase, tid);
}

// ---------------------------------------------------------------------------
extern "C" void kernel_launch(void* const* d_in, const int* in_sizes, int n_in,
                              void* d_out, int out_size) {
    (void)in_sizes; (void)n_in; (void)out_size;

    PPP pp;
    pp.w[0] = (const float*)d_in[2];  pp.w[1] = (const float*)d_in[4];
    pp.w[2] = (const float*)d_in[6];  pp.w[3] = (const float*)d_in[8];
    pp.w[4] = (const float*)d_in[10]; pp.w[5] = (const float*)d_in[12];
    pp.w[6] = (const float*)d_in[14]; pp.w[7] = (const float*)d_in[16];
    pp.w[8] = (const float*)d_in[18]; pp.w[9] = (const float*)d_in[20];
    pp.w[10] = (const float*)d_in[22];
    preproc_all<<<896, 256>>>(pp);

    float* scr = nullptr;  cudaGetSymbolAddress((void**)&scr, g_scr);
    bf16*  bfp = nullptr;  cudaGetSymbolAddress((void**)&bfp, g_bf);
    float* S0 = scr;
    float* S1 = scr + 1ull * NTOT;
    float* S2 = scr + 2ull * NTOT;
    float* S3 = scr + 3ull * NTOT;
    float* S4 = scr + 4ull * NTOT;
    bf16* P0 = bfp;
    bf16* P1 = bfp + 2ull * NTOT;
    bf16* P2 = bfp + 4ull * NTOT;
    bf16* P3 = bfp + 6ull * NTOT;
    bf16* P4 = bfp + 8ull * NTOT;
    bf16* P5 = bfp + 10ull * NTOT;

    const float* F_opt = (const float*)d_in[0];
    const float* F_sar = (const float*)d_in[1];
    float* out = (float*)d_out;

    conv_pair<<<8192, 256>>>(F_opt, F_sar, P0, P1);

    cudaFuncSetAttribute(gemm_k<EPI_BIAS>,
                         cudaFuncAttributeMaxDynamicSharedMemorySize, SMEM_G);
    cudaFuncSetAttribute(gemm_k<EPI_NONE>,
                         cudaFuncAttributeMaxDynamicSharedMemorySize, SMEM_G);
    cudaFuncSetAttribute(gemm_k<EPI_PROJ>,
                         cudaFuncAttributeMaxDynamicSharedMemorySize, SMEM_G);
    cudaFuncSetAttribute(gemm_k<EPI_GATEACC>,
                         cudaFuncAttributeMaxDynamicSharedMemorySize, SMEM_G);
    cudaFuncSetAttribute(gemm_k<EPI_FUSEACC>,
                         cudaFuncAttributeMaxDynamicSharedMemorySize, SMEM_G);
    cudaFuncSetAttribute(attn_k,
                         cudaFuncAttributeMaxDynamicSharedMemorySize, SMEM_A);

    const bf16* W = g_w2;  // device-side symbol usable for pointer arithmetic
    bf16* w2p = nullptr;   cudaGetSymbolAddress((void**)&w2p, g_w2);
    (void)W;

    // 1) QKV: 6 matrices, one launch
    {
        GP g{};
        const int wo[6] = {OW_QO, OW_KO, OW_VO, OW_QS, OW_KS, OW_VS};
        const int bi[6] = {3, 5, 7, 9, 11, 13};
        float* ds[6] = {S0, S1, S2, S3, S4, nullptr};
        // S5 doesn't exist; Vs goes to... use out as temp for Vs (overwritten later)
        ds[5] = out;  // temp: Vs in out[0..NTOT) — final fuse writes it last
        for (int i = 0; i < 6; ++i) {
            g.xh[i] = (i < 3) ? P0 : P1;
            g.wh[i] = w2p + wo[i];
            g.wl[i] = w2p + wo[i] + 16384;
            g.bias[i] = (const float*)d_in[bi[i]];
            g.dst[i] = ds[i];
        }
        g.wstride = 128;
        gemm_k<EPI_BIAS><<<6144, TB, SMEM_G>>>(g);
    }

    // 2) attention: o2s(Qo=S0, Ks=S4, Vs=out) -> P2 ; s2o(Qs=S3, Ko=S1, Vo=S2) -> P3
    {
        AP a{S0, S4, out, S3, S1, S2, P2, P3};
        attn_k<<<8192, TB, SMEM_A>>>(a);
    }

    // 3) projections: P2 -> S0(f32)+P4 ; P3 -> S1(f32)+P5
    {
        GP g{};
        g.xh[0] = P2; g.wh[0] = w2p + OW_PO; g.wl[0] = w2p + OW_PO + 16384;
        g.bias[0] = (const float*)d_in[15]; g.dst[0] = S0; g.dpair[0] = P4;
        g.xh[1] = P3; g.wh[1] = w2p + OW_PS; g.wl[1] = w2p + OW_PS + 16384;
        g.bias[1] = (const float*)d_in[17]; g.dst[1] = S1; g.dpair[1] = P5;
        g.wstride = 128;
        gemm_k<EPI_PROJ><<<2048, TB, SMEM_G>>>(g);
    }

    // 4) gate pass1 (K-half 0, X = F pair): -> S2, S3 (fp32 tmp)
    {
        GP g{};
        g.xh[0] = P0; g.wh[0] = w2p + OW_GO; g.wl[0] = w2p + OW_GO + 32768;
        g.dst[0] = S2;
        g.xh[1] = P1; g.wh[1] = w2p + OW_GS; g.wl[1] = w2p + OW_GS + 32768;
        g.dst[1] = S3;
        g.wstride = 256;
        gemm_k<EPI_NONE><<<2048, TB, SMEM_G>>>(g);
    }
    // 5) gate pass2 (K-half 1, X = proj pair, acc = tmp): sigma + F_new pair
    {
        GP g{};
        g.xh[0] = P4; g.wh[0] = w2p + OW_GO + 128; g.wl[0] = w2p + OW_GO + 32768 + 128;
        g.bias[0] = (const float*)d_in[19]; g.dst[0] = out + NTOT; g.dpair[0] = P2;
        g.acc[0] = S2; g.f32a[0] = F_opt; g.f32b[0] = S0;
        g.xh[1] = P5; g.wh[1] = w2p + OW_GS + 128; g.wl[1] = w2p + OW_GS + 32768 + 128;
        g.bias[1] = (const float*)d_in[21]; g.dst[1] = out + 2 * NTOT; g.dpair[1] = P3;
        g.acc[1] = S3; g.f32a[1] = F_sar; g.f32b[1] = S1;
        g.wstride = 256;
        gemm_k<EPI_GATEACC><<<2048, TB, SMEM_G>>>(g);
    }

    // 6) fuse pass1 (K-half 0, X = F_opt_new pair P2): -> S4
    {
        GP g{};
        g.xh[0] = P2; g.wh[0] = w2p + OW_FW; g.wl[0] = w2p + OW_FW + 32768;
        g.dst[0] = S4;
        g.wstride = 256;
        gemm_k<EPI_NONE><<<1024, TB, SMEM_G>>>(g);
    }
    // 7) fuse pass2 (K-half 1, X = F_sar_new pair P3, acc = S4): BN+SiLU -> out
    {
        GP g{};
        g.xh[0] = P3; g.wh[0] = w2p + OW_FW + 128; g.wl[0] = w2p + OW_FW + 32768 + 128;
        g.bias[0] = (const float*)d_in[23]; g.dst[0] = out; g.acc[0] = S4;
        g.gma = (const float*)d_in[24]; g.bta = (const float*)d_in[25];
        g.mu  = (const float*)d_in[26]; g.var = (const float*)d_in[27];
        g.wstride = 256;
        gemm_k<EPI_FUSEACC><<<1024, TB, SMEM_G>>>(g);
    }
}